// round 4
// baseline (speedup 1.0000x reference)
#include <cuda_runtime.h>
#include <cuda_bf16.h>
#include <math.h>

#define N_NODES 100000
#define N_EDGES 1600000
#define HID 64

// ---------------- scratch (static device memory; no allocations) ----------------
__device__ int   g_deg[N_NODES];
__device__ float g_dinv[N_NODES];
__device__ int   g_rowptr[N_NODES + 1];
__device__ int   g_fill[N_NODES];
__device__ int   g_esrc[N_EDGES];
__device__ int   g_edst[N_EDGES];
__device__ int2  g_csr[N_EDGES];            // .x = src, .y = bits of norm weight
__device__ float g_h1[(size_t)N_NODES * HID];
__device__ float g_h2[(size_t)N_NODES * HID];
__device__ int   g_tilesum[1024];

// ---------------- preprocessing kernels ----------------
__global__ void k_init_deg() {
    int i = blockIdx.x * blockDim.x + threadIdx.x;
    if (i < N_NODES) g_deg[i] = 1;   // self-loop
}

// edge_index arrives as int32 (harness delivers int64 refs downcast to int32).
__global__ void k_hist(const int* __restrict__ ei) {
    int e = blockIdx.x * blockDim.x + threadIdx.x;
    if (e < N_EDGES) {
        int s = ei[e];
        int d = ei[N_EDGES + e];
        // defensive: invalid indices become self-referential no-ops instead of faults
        if ((unsigned)s >= N_NODES) s = 0;
        if ((unsigned)d >= N_NODES) d = 0;
        g_esrc[e] = s;
        g_edst[e] = d;
        atomicAdd(&g_deg[d], 1);
    }
}

__global__ void k_dinv() {
    int i = blockIdx.x * blockDim.x + threadIdx.x;
    if (i < N_NODES) g_dinv[i] = rsqrtf((float)g_deg[i]);  // deg >= 1 always
}

#define SCAN_TILES 1024
#define SCAN_TS    98            // 98*1024 >= 100000

__global__ void k_scanA() {
    int t = blockIdx.x * blockDim.x + threadIdx.x;
    if (t >= SCAN_TILES) return;
    int start = t * SCAN_TS;
    int end = min(start + SCAN_TS, N_NODES);
    int sum = 0;
    for (int i = start; i < end; i++) sum += g_deg[i] - 1;
    g_tilesum[t] = sum;
}

__global__ void k_scanB() {
    __shared__ int s[SCAN_TILES];
    int t = threadIdx.x;
    int v = g_tilesum[t];
    s[t] = v;
    __syncthreads();
    for (int off = 1; off < SCAN_TILES; off <<= 1) {
        int a = (t >= off) ? s[t - off] : 0;
        __syncthreads();
        s[t] += a;
        __syncthreads();
    }
    g_tilesum[t] = s[t] - v;                 // exclusive
    if (t == SCAN_TILES - 1) g_rowptr[N_NODES] = s[t];
}

__global__ void k_scanC() {
    int t = blockIdx.x * blockDim.x + threadIdx.x;
    if (t >= SCAN_TILES) return;
    int start = t * SCAN_TS;
    int end = min(start + SCAN_TS, N_NODES);
    int run = g_tilesum[t];
    for (int i = start; i < end; i++) {
        g_rowptr[i] = run;
        g_fill[i] = run;
        run += g_deg[i] - 1;
    }
}

__global__ void k_scatter() {
    int e = blockIdx.x * blockDim.x + threadIdx.x;
    if (e < N_EDGES) {
        int s = g_esrc[e];
        int d = g_edst[e];
        int pos = atomicAdd(&g_fill[d], 1);
        if ((unsigned)pos < N_EDGES) {
            float w = g_dinv[s] * g_dinv[d];
            g_csr[pos] = make_int2(s, __float_as_int(w));
        }
    }
}

// ---------------- GEMM: g_h1[N,64] = X[N,KDIM] @ W[KDIM,64] ----------------
// Block = 128 threads, one row per thread, 64 fp32 accumulators.
// K processed in chunks of 32. Static smem only (24.2 KB):
//   Ws[32][64]  : W chunk, read as float4 broadcast (conflict-free)
//   xs[32][129] : x chunk transposed; stride 129 => conflict-free stores+loads
// SRC = 0: read from param Xp (layer-1 input x). SRC = 1: read from g_h2.
template <int KDIM, int SRC>
__global__ void k_gemm(const float* __restrict__ Xp, const float* __restrict__ W) {
    __shared__ float Ws[32 * 64];
    __shared__ float xs[32 * 129];
    const float* __restrict__ X = (SRC == 0) ? Xp : (const float*)g_h2;

    int tid = threadIdx.x;
    int base = blockIdx.x * 128;

    float acc[64];
#pragma unroll
    for (int c = 0; c < 64; c++) acc[c] = 0.f;

    for (int k0 = 0; k0 < KDIM; k0 += 32) {
        __syncthreads();   // previous chunk fully consumed
        // W chunk: 512 float4, 4 per thread
#pragma unroll
        for (int it = 0; it < 4; it++) {
            int idx = tid + 128 * it;
            ((float4*)Ws)[idx] = ((const float4*)W)[k0 * 16 + idx];
        }
        // x chunk: 1024 float4, 8 per thread; store transposed into xs[u][r]
#pragma unroll
        for (int it = 0; it < 8; it++) {
            int idx = tid + 128 * it;          // 0..1023
            int r = idx >> 3;                  // 0..127
            int u4 = idx & 7;                  // 0..7  (k offset u4*4)
            float4 v = make_float4(0.f, 0.f, 0.f, 0.f);
            int grow = base + r;
            if (grow < N_NODES)
                v = *(const float4*)&X[(size_t)grow * KDIM + k0 + u4 * 4];
            xs[(u4 * 4 + 0) * 129 + r] = v.x;
            xs[(u4 * 4 + 1) * 129 + r] = v.y;
            xs[(u4 * 4 + 2) * 129 + r] = v.z;
            xs[(u4 * 4 + 3) * 129 + r] = v.w;
        }
        __syncthreads();
#pragma unroll 4
        for (int u = 0; u < 32; u++) {
            float xv = xs[u * 129 + tid];
            const float4* Wr = (const float4*)&Ws[u * 64];
#pragma unroll
            for (int cc = 0; cc < 16; cc++) {
                float4 wv = Wr[cc];
                acc[cc * 4 + 0] += xv * wv.x;
                acc[cc * 4 + 1] += xv * wv.y;
                acc[cc * 4 + 2] += xv * wv.z;
                acc[cc * 4 + 3] += xv * wv.w;
            }
        }
    }
    int row = base + tid;
    if (row < N_NODES) {
        float4* o = (float4*)&g_h1[(size_t)row * 64];
#pragma unroll
        for (int cc = 0; cc < 16; cc++)
            o[cc] = make_float4(acc[cc * 4 + 0], acc[cc * 4 + 1],
                                acc[cc * 4 + 2], acc[cc * 4 + 3]);
    }
}

// ---------------- Aggregation + epilogue: warp per node ----------------
// OUT[i] = sum_{e: dst=i} w_e * g_h1[src_e] + dinv[i]^2 * g_h1[i] + bias
// MODE=1: relu + L2-normalize, writes g_h2.  MODE=0: plain, writes OUTp.
template <int MODE>
__global__ void k_agg(const float* __restrict__ bias, float* __restrict__ OUTp) {
    int gwarp = (blockIdx.x * blockDim.x + threadIdx.x) >> 5;
    int lane = threadIdx.x & 31;
    if (gwarp >= N_NODES) return;
    int i = gwarp;

    float di = g_dinv[i];
    int beg = g_rowptr[i];
    int end = g_rowptr[i + 1];

    const float2* __restrict__ H2 = (const float2*)g_h1;
    float2 hv = H2[(size_t)i * 32 + lane];
    float wself = di * di;
    float a0 = wself * hv.x;
    float a1 = wself * hv.y;

    for (int j = beg; j < end; j++) {
        int2 sw = g_csr[j];                    // broadcast across warp
        float w = __int_as_float(sw.y);
        float2 hs = H2[(size_t)sw.x * 32 + lane];
        a0 += w * hs.x;
        a1 += w * hs.y;
    }

    float2 b = ((const float2*)bias)[lane];
    a0 += b.x;
    a1 += b.y;

    if (MODE == 1) {
        a0 = fmaxf(a0, 0.f);
        a1 = fmaxf(a1, 0.f);
        float ss = a0 * a0 + a1 * a1;
#pragma unroll
        for (int o = 16; o; o >>= 1) ss += __shfl_xor_sync(0xffffffffu, ss, o);
        float inv = 1.f / fmaxf(sqrtf(ss), 1e-12f);
        a0 *= inv;
        a1 *= inv;
        ((float2*)g_h2)[(size_t)i * 32 + lane] = make_float2(a0, a1);
    } else {
        ((float2*)OUTp)[(size_t)i * 32 + lane] = make_float2(a0, a1);
    }
}

// ---------------- launch ----------------
extern "C" void kernel_launch(void* const* d_in, const int* in_sizes, int n_in,
                              void* d_out, int out_size) {
    const float* x = (const float*)d_in[0];
    const int* ei = (const int*)d_in[1];     // int32 edge_index [2, E]
    const float* W1 = (const float*)d_in[2];
    const float* b1 = (const float*)d_in[3];
    const float* W2 = (const float*)d_in[4];
    const float* b2 = (const float*)d_in[5];
    const float* W3 = (const float*)d_in[6];
    const float* b3 = (const float*)d_in[7];
    float* out = (float*)d_out;

    const int T = 256;
    // graph preprocessing (rebuilt every replay — deterministic)
    k_init_deg<<<(N_NODES + T - 1) / T, T>>>();
    k_hist<<<(N_EDGES + T - 1) / T, T>>>(ei);
    k_dinv<<<(N_NODES + T - 1) / T, T>>>();
    k_scanA<<<4, 256>>>();
    k_scanB<<<1, 1024>>>();
    k_scanC<<<4, 256>>>();
    k_scatter<<<(N_EDGES + T - 1) / T, T>>>();

    int gemm_grid = (N_NODES + 127) / 128;
    int agg_grid = (N_NODES * 32 + T - 1) / T;

    // layer 1: x @ W1 -> g_h1 ; agg+relu+l2norm -> g_h2
    k_gemm<256, 0><<<gemm_grid, 128>>>(x, W1);
    k_agg<1><<<agg_grid, T>>>(b1, nullptr);
    // layer 2: g_h2 @ W2 -> g_h1 ; agg+relu+l2norm -> g_h2
    k_gemm<64, 1><<<gemm_grid, 128>>>(nullptr, W2);
    k_agg<1><<<agg_grid, T>>>(b2, nullptr);
    // layer 3: g_h2 @ W3 -> g_h1 ; plain agg -> out
    k_gemm<64, 1><<<gemm_grid, 128>>>(nullptr, W3);
    k_agg<0><<<agg_grid, T>>>(b3, out);
}